// round 8
// baseline (speedup 1.0000x reference)
#include <cuda_runtime.h>
#include <math_constants.h>
#include <cstdint>

// FCOS decode — per-warp cp.async.bulk (TMA-engine) rings; inputs never touch the LSU.
//   inputs  : bbox [16,128,128,4] f32, center [16,128,128,1] f32, cls [16,128,128,80] f32
//   outputs : xywh [16,16384,4] f32 ++ cls_idx [16,16384] (as f32) ++ conf [16,16384] f32

#define N_LOC      (16 * 128 * 128)   // 262144
#define N_CLS      80
#define XYWH_ELEMS (N_LOC * 4)

#define THREADS        128
#define WARPS          (THREADS / 32)            // 4
#define WTILE          8                         // locations per stage
#define F4_PER_ROW     (N_CLS / 4)               // 20
#define F4_CLS         (WTILE * F4_PER_ROW)      // 160
#define CLS_BYTES      (F4_CLS * 16)             // 2560
#define BBOX_BYTES     (WTILE * 16)              // 128
#define CTR_BYTES      (WTILE * 4)               // 32
#define STAGE_F4       (F4_CLS + WTILE + 2)      // 170 f4 = 2720 B
#define STAGE_BYTES    (STAGE_F4 * 16)           // 2720
#define BBOX_OFF_F4    F4_CLS                    // 160
#define CTR_OFF_F4     (F4_CLS + WTILE)          // 168
#define STAGES         4
#define N_WTILES       (N_LOC / WTILE)           // 32768

#define NUM_SMS        148
#define BLOCKS_PER_SM  5
#define GRID           (NUM_SMS * BLOCKS_PER_SM) // 740

__device__ __forceinline__ float4 fmax4(float4 a, float4 b) {
    float4 r;
    r.x = fmaxf(a.x, b.x); r.y = fmaxf(a.y, b.y);
    r.z = fmaxf(a.z, b.z); r.w = fmaxf(a.w, b.w);
    return r;
}
__device__ __forceinline__ unsigned smem_u32(const void* p) {
    return (unsigned)__cvta_generic_to_shared(p);
}
__device__ __forceinline__ void mbar_init(unsigned bar, unsigned count) {
    asm volatile("mbarrier.init.shared.b64 [%0], %1;" :: "r"(bar), "r"(count) : "memory");
}
__device__ __forceinline__ void mbar_expect_tx(unsigned bar, unsigned bytes) {
    asm volatile("mbarrier.arrive.expect_tx.shared.b64 _, [%0], %1;"
                 :: "r"(bar), "r"(bytes) : "memory");
}
__device__ __forceinline__ void bulk_g2s(unsigned dst, const void* src,
                                         unsigned bytes, unsigned bar) {
    asm volatile("cp.async.bulk.shared::cta.global.mbarrier::complete_tx::bytes "
                 "[%0], [%1], %2, [%3];"
                 :: "r"(dst), "l"(src), "r"(bytes), "r"(bar) : "memory");
}
__device__ __forceinline__ void mbar_wait(unsigned bar, unsigned parity) {
    asm volatile(
        "{\n\t"
        ".reg .pred P;\n\t"
        "WAIT_%=:\n\t"
        "mbarrier.try_wait.parity.shared.b64 P, [%0], %1, 0x989680;\n\t"
        "@P bra.uni DONE_%=;\n\t"
        "bra.uni WAIT_%=;\n\t"
        "DONE_%=:\n\t"
        "}"
        :: "r"(bar), "r"(parity) : "memory");
}

__global__ __launch_bounds__(THREADS)
void fcos_decode_kernel(const float* __restrict__ cls,
                        const float* __restrict__ bbox,
                        const float* __restrict__ center,
                        float* __restrict__ out)
{
    __shared__ float4   sm[WARPS][STAGES][STAGE_F4];   // 42.5 KB
    __shared__ uint64_t mbar[WARPS][STAGES];

    const int lane = threadIdx.x & 31;
    const int wid  = threadIdx.x >> 5;
    const int wgid = blockIdx.x * WARPS + wid;         // global warp id
    const int W    = GRID * WARPS;                     // 2960 warps
    const int row  = lane >> 2;   // 0..7 (location within tile)
    const int part = lane & 3;    // 0..3 (20-class segment)

    if (threadIdx.x == 0) {
        for (int i = 0; i < WARPS * STAGES; ++i)
            mbar_init(smem_u32(&mbar[0][0] + i), 1);
        asm volatile("fence.proxy.async.shared::cta;" ::: "memory");
    }
    __syncthreads();

    float4 (*buf)[STAGE_F4] = sm[wid];
    unsigned bars[STAGES];
    #pragma unroll
    for (int s = 0; s < STAGES; ++s) bars[s] = smem_u32(&mbar[wid][s]);

    // ---- prologue: issue tiles for iterations 0..STAGES-2 ----
    int issue = wgid;
    #pragma unroll
    for (int s = 0; s < STAGES - 1; ++s) {
        if (lane == 0 && issue < N_WTILES) {
            mbar_expect_tx(bars[s], STAGE_BYTES);
            bulk_g2s(smem_u32(&buf[s][0]),          cls    + (size_t)issue * (WTILE * N_CLS), CLS_BYTES,  bars[s]);
            bulk_g2s(smem_u32(&buf[s][BBOX_OFF_F4]), bbox  + (size_t)issue * (WTILE * 4),     BBOX_BYTES, bars[s]);
            bulk_g2s(smem_u32(&buf[s][CTR_OFF_F4]),  center + (size_t)issue * WTILE,          CTR_BYTES,  bars[s]);
        }
        issue += W;
    }

    int bi = 0, phase = 0;
    for (int k = wgid; k < N_WTILES; k += W) {
        // ---- issue iteration k+STAGES-1 into the slot consumed last iteration ----
        {
            int ib = bi + (STAGES - 1);
            if (ib >= STAGES) ib -= STAGES;
            if (lane == 0 && issue < N_WTILES) {
                mbar_expect_tx(bars[ib], STAGE_BYTES);
                bulk_g2s(smem_u32(&buf[ib][0]),           cls    + (size_t)issue * (WTILE * N_CLS), CLS_BYTES,  bars[ib]);
                bulk_g2s(smem_u32(&buf[ib][BBOX_OFF_F4]), bbox   + (size_t)issue * (WTILE * 4),     BBOX_BYTES, bars[ib]);
                bulk_g2s(smem_u32(&buf[ib][CTR_OFF_F4]),  center + (size_t)issue * WTILE,           CTR_BYTES,  bars[ib]);
            }
            issue += W;
        }

        // ---- wait for this iteration's tile ----
        mbar_wait(bars[bi], phase);

        // ---- load my 20 classes ----
        const float4* my = &buf[bi][row * F4_PER_ROW + part * 5];
        float4 v0 = my[0], v1 = my[1], v2 = my[2], v3 = my[3], v4 = my[4];

        // ---- max via shallow FMNMX tree (sigmoid monotonic -> raw logits) ----
        float4 a = fmax4(fmax4(v0, v1), fmax4(v2, v3));
        a = fmax4(a, v4);
        float best = fmaxf(fmaxf(a.x, a.y), fmaxf(a.z, a.w));

        // ---- first index equal to max: independent compares + min tree ----
        const int b0 = part * 20;
        int c0 = (v0.x == best) ? b0 + 0  : 1023;
        int c1 = (v0.y == best) ? b0 + 1  : 1023;
        int c2 = (v0.z == best) ? b0 + 2  : 1023;
        int c3 = (v0.w == best) ? b0 + 3  : 1023;
        int c4 = (v1.x == best) ? b0 + 4  : 1023;
        int c5 = (v1.y == best) ? b0 + 5  : 1023;
        int c6 = (v1.z == best) ? b0 + 6  : 1023;
        int c7 = (v1.w == best) ? b0 + 7  : 1023;
        int c8 = (v2.x == best) ? b0 + 8  : 1023;
        int c9 = (v2.y == best) ? b0 + 9  : 1023;
        int ca = (v2.z == best) ? b0 + 10 : 1023;
        int cb = (v2.w == best) ? b0 + 11 : 1023;
        int cc = (v3.x == best) ? b0 + 12 : 1023;
        int cd = (v3.y == best) ? b0 + 13 : 1023;
        int ce = (v3.z == best) ? b0 + 14 : 1023;
        int cf = (v3.w == best) ? b0 + 15 : 1023;
        int cg = (v4.x == best) ? b0 + 16 : 1023;
        int ch = (v4.y == best) ? b0 + 17 : 1023;
        int ci = (v4.z == best) ? b0 + 18 : 1023;
        int cj = (v4.w == best) ? b0 + 19 : 1023;
        int bidx = min(min(min(min(c0, c1), min(c2, c3)),
                           min(min(c4, c5), min(c6, c7))),
                       min(min(min(c8, c9), min(ca, cb)),
                           min(min(cc, cd), min(ce, cf))));
        bidx = min(bidx, min(min(cg, ch), min(ci, cj)));

        // ---- combine 4 segment-partials (tie -> lowest class index) ----
        #pragma unroll
        for (int off = 1; off <= 2; off <<= 1) {
            float ob = __shfl_xor_sync(0xffffffffu, best, off);
            int   oi = __shfl_xor_sync(0xffffffffu, bidx, off);
            if (ob > best || (ob == best && oi < bidx)) { best = ob; bidx = oi; }
        }

        // ---- owner lane: bbox decode + confidence + writes (inputs from smem) ----
        if (part == 0) {
            int loc = k * WTILE + row;

            float4 bb = buf[bi][BBOX_OFF_F4 + row];
            float l  = __expf(bb.x) * 8.0f;
            float tt = __expf(bb.y) * 8.0f;
            float r  = __expf(bb.z) * 8.0f;
            float bo = __expf(bb.w) * 8.0f;

            int h = (loc >> 7) & 127;
            int w =  loc       & 127;

            float4 xywh;
            xywh.x = ((float)w * 8.0f + 4.0f) - (l  - r ) * 0.5f;
            xywh.y = ((float)h * 8.0f + 4.0f) - (tt - bo) * 0.5f;
            xywh.z = l  + r;
            xywh.w = tt + bo;

            float ctr = reinterpret_cast<const float*>(&buf[bi][CTR_OFF_F4])[row];
            float s_ctr = 1.0f / (1.0f + __expf(-ctr));
            float s_cls = 1.0f / (1.0f + __expf(-best));

            __stcs(&reinterpret_cast<float4*>(out)[loc], xywh);
            __stcs(&out[XYWH_ELEMS + loc], (float)bidx);
            __stcs(&out[XYWH_ELEMS + N_LOC + loc], sqrtf(s_ctr * s_cls));
        }

        __syncwarp();   // keep warp converged; all reads of buf[bi] retired
        ++bi;
        if (bi == STAGES) { bi = 0; phase ^= 1; }
    }
}

extern "C" void kernel_launch(void* const* d_in, const int* in_sizes, int n_in,
                              void* d_out, int out_size)
{
    const float* bbox   = (const float*)d_in[0];
    const float* center = (const float*)d_in[1];
    const float* cls    = (const float*)d_in[2];
    float* out = (float*)d_out;

    fcos_decode_kernel<<<GRID, THREADS>>>(cls, bbox, center, out);
}

// round 9
// speedup vs baseline: 1.2931x; 1.2931x over previous
#include <cuda_runtime.h>
#include <math_constants.h>
#include <cstdint>

// FCOS decode — warp-decoupled 2-stage cp.async.cg pipelines carrying ALL inputs
// (cls + bbox + center) so the consume phase never touches global memory.
//   inputs  : bbox [16,128,128,4] f32, center [16,128,128,1] f32, cls [16,128,128,80] f32
//   outputs : xywh [16,16384,4] f32 ++ cls_idx [16,16384] (as f32) ++ conf [16,16384] f32

#define N_LOC      (16 * 128 * 128)   // 262144
#define N_CLS      80
#define XYWH_ELEMS (N_LOC * 4)

#define THREADS        128
#define WARPS          (THREADS / 32)            // 4
#define WTILE          8                         // locations per stage
#define F4_PER_ROW     (N_CLS / 4)               // 20
#define F4_CLS         (WTILE * F4_PER_ROW)      // 160
#define BBOX_OFF       F4_CLS                    // f4 index 160
#define CTR_OFF        (F4_CLS + WTILE)          // f4 index 168
#define STAGE_F4       (F4_CLS + WTILE + 2)      // 170 f4 = 2720 B
#define STAGES         2
#define N_WTILES       (N_LOC / WTILE)           // 32768

#define NUM_SMS        148
#define BLOCKS_PER_SM  10
#define GRID           (NUM_SMS * BLOCKS_PER_SM) // 1480

__device__ __forceinline__ float4 fmax4(float4 a, float4 b) {
    float4 r;
    r.x = fmaxf(a.x, b.x); r.y = fmaxf(a.y, b.y);
    r.z = fmaxf(a.z, b.z); r.w = fmaxf(a.w, b.w);
    return r;
}
__device__ __forceinline__ void cp_cg16(void* smem_dst, const void* gsrc) {
    unsigned d = (unsigned)__cvta_generic_to_shared(smem_dst);
    asm volatile("cp.async.cg.shared.global [%0], [%1], 16;"
                 :: "r"(d), "l"(gsrc) : "memory");
}
__device__ __forceinline__ void cp_commit() {
    asm volatile("cp.async.commit_group;" ::: "memory");
}
__device__ __forceinline__ void cp_wait1() {
    asm volatile("cp.async.wait_group 1;" ::: "memory");
}

__global__ __launch_bounds__(THREADS, BLOCKS_PER_SM)
void fcos_decode_kernel(const float4* __restrict__ cls4,
                        const float4* __restrict__ bbox4,
                        const float4* __restrict__ ctr4,
                        float* __restrict__ out)
{
    __shared__ float4 sm[WARPS][STAGES][STAGE_F4];   // 21.25 KB

    const int lane = threadIdx.x & 31;
    const int wid  = threadIdx.x >> 5;
    const int wgid = blockIdx.x * WARPS + wid;       // global warp id
    const int W    = GRID * WARPS;                   // 5920 warps
    const int row  = lane >> 2;   // 0..7 (location within tile)
    const int part = lane & 3;    // 0..3 (20-class segment)

    float4 (*buf)[STAGE_F4] = sm[wid];

    // issue one tile's worth of cp.async (cls + bbox + center) into slot s
    auto issue_tile = [&](int s, int tile) {
        const float4* csrc = cls4 + (size_t)tile * F4_CLS;
        #pragma unroll
        for (int i = 0; i < 5; ++i)
            cp_cg16(&buf[s][lane + 32 * i], &csrc[lane + 32 * i]);
        if (lane < WTILE)
            cp_cg16(&buf[s][BBOX_OFF + lane], &bbox4[(size_t)tile * WTILE + lane]);
        if (lane < 2)
            cp_cg16(&buf[s][CTR_OFF + lane], &ctr4[(size_t)tile * 2 + lane]);
    };

    // ---- prologue: issue tile for iteration 0 ----
    int issue = wgid;
    if (issue < N_WTILES) issue_tile(0, issue);
    cp_commit();
    issue += W;

    int bi = 0;
    for (int k = wgid; k < N_WTILES; k += W) {
        // ---- issue next iteration's tile into the other buffer ----
        if (issue < N_WTILES) issue_tile(bi ^ 1, issue);
        cp_commit();
        issue += W;

        cp_wait1();     // current tile's group complete (next still in flight)
        __syncwarp();   // cross-lane smem visibility

        // ---- load my 20 classes ----
        const float4* my = &buf[bi][row * F4_PER_ROW + part * 5];
        float4 v0 = my[0], v1 = my[1], v2 = my[2], v3 = my[3], v4 = my[4];

        // ---- max via shallow FMNMX tree (sigmoid monotonic -> raw logits) ----
        float4 a = fmax4(fmax4(v0, v1), fmax4(v2, v3));
        a = fmax4(a, v4);
        float best = fmaxf(fmaxf(a.x, a.y), fmaxf(a.z, a.w));

        // ---- first index equal to max: independent compares + min tree ----
        const int b0 = part * 20;
        int c0 = (v0.x == best) ? b0 + 0  : 1023;
        int c1 = (v0.y == best) ? b0 + 1  : 1023;
        int c2 = (v0.z == best) ? b0 + 2  : 1023;
        int c3 = (v0.w == best) ? b0 + 3  : 1023;
        int c4 = (v1.x == best) ? b0 + 4  : 1023;
        int c5 = (v1.y == best) ? b0 + 5  : 1023;
        int c6 = (v1.z == best) ? b0 + 6  : 1023;
        int c7 = (v1.w == best) ? b0 + 7  : 1023;
        int c8 = (v2.x == best) ? b0 + 8  : 1023;
        int c9 = (v2.y == best) ? b0 + 9  : 1023;
        int ca = (v2.z == best) ? b0 + 10 : 1023;
        int cb = (v2.w == best) ? b0 + 11 : 1023;
        int cc = (v3.x == best) ? b0 + 12 : 1023;
        int cd = (v3.y == best) ? b0 + 13 : 1023;
        int ce = (v3.z == best) ? b0 + 14 : 1023;
        int cf = (v3.w == best) ? b0 + 15 : 1023;
        int cg = (v4.x == best) ? b0 + 16 : 1023;
        int ch = (v4.y == best) ? b0 + 17 : 1023;
        int ci = (v4.z == best) ? b0 + 18 : 1023;
        int cj = (v4.w == best) ? b0 + 19 : 1023;
        int bidx = min(min(min(min(c0, c1), min(c2, c3)),
                           min(min(c4, c5), min(c6, c7))),
                       min(min(min(c8, c9), min(ca, cb)),
                           min(min(cc, cd), min(ce, cf))));
        bidx = min(bidx, min(min(cg, ch), min(ci, cj)));

        // ---- combine 4 segment-partials (tie -> lowest class index) ----
        #pragma unroll
        for (int off = 1; off <= 2; off <<= 1) {
            float ob = __shfl_xor_sync(0xffffffffu, best, off);
            int   oi = __shfl_xor_sync(0xffffffffu, bidx, off);
            if (ob > best || (ob == best && oi < bidx)) { best = ob; bidx = oi; }
        }

        // ---- owner lane: bbox decode + confidence + writes (all inputs in smem) ----
        if (part == 0) {
            int loc = k * WTILE + row;

            float4 bb = buf[bi][BBOX_OFF + row];
            float l  = __expf(bb.x) * 8.0f;
            float tt = __expf(bb.y) * 8.0f;
            float r  = __expf(bb.z) * 8.0f;
            float bo = __expf(bb.w) * 8.0f;

            int h = (loc >> 7) & 127;
            int w =  loc       & 127;

            float4 xywh;
            xywh.x = ((float)w * 8.0f + 4.0f) - (l  - r ) * 0.5f;
            xywh.y = ((float)h * 8.0f + 4.0f) - (tt - bo) * 0.5f;
            xywh.z = l  + r;
            xywh.w = tt + bo;

            float ctr = reinterpret_cast<const float*>(&buf[bi][CTR_OFF])[row];
            // conf = sqrt(sigmoid(ctr)*sigmoid(best)) = rsqrt((1+e^-ctr)(1+e^-best))
            float ea = __expf(-ctr);
            float eb = __expf(-best);
            float conf = rsqrtf((1.0f + ea) * (1.0f + eb));

            __stcs(&reinterpret_cast<float4*>(out)[loc], xywh);
            __stcs(&out[XYWH_ELEMS + loc], (float)bidx);
            __stcs(&out[XYWH_ELEMS + N_LOC + loc], conf);
        }

        __syncwarp();   // lanes done reading buf[bi] before next iter refills it
        bi ^= 1;
    }
}

extern "C" void kernel_launch(void* const* d_in, const int* in_sizes, int n_in,
                              void* d_out, int out_size)
{
    const float* bbox   = (const float*)d_in[0];
    const float* center = (const float*)d_in[1];
    const float* cls    = (const float*)d_in[2];
    float* out = (float*)d_out;

    fcos_decode_kernel<<<GRID, THREADS>>>(
        reinterpret_cast<const float4*>(cls),
        reinterpret_cast<const float4*>(bbox),
        reinterpret_cast<const float4*>(center),
        out);
}